// round 6
// baseline (speedup 1.0000x reference)
#include <cuda_runtime.h>

#define NV 6890
#define NJ 24
#define NBD 10
#define NBATCH 256
#define NP 100
#define BT 16           // batches per k_verts block
#define VB_Y 16         // NBATCH / BT
#define VB_X 27         // ceil(3445/128): 2 verts per thread
#define PL_Y 10         // extra grid.y rows for plane blocks (27*10=270 >= 256)

// scratch (allocation-free rule: __device__ globals)
__device__ float g_vshaped[NV * 3];
__device__ float g_joints[NJ * 3];
__device__ float g_A[NBATCH * NJ * 12];   // per (b,j): R row-major [0..8], t [9..11]
__device__ float g_wT[NJ * NV];           // transposed lbs weights [j][v]

__constant__ int c_parents[NJ] = {-1,0,0,0,1,2,3,4,5,6,7,8,9,9,9,12,13,14,16,17,18,19,20,21};
__constant__ int c_level[NJ]   = { 0,1,1,1,2,2,2,3,3,3,4,4,4,4, 4, 5, 5, 5, 6, 6, 7, 8, 9,10};

// packed fp32x2 FMA: d = a*b + d  (FFMA2 — only reachable via PTX)
__device__ __forceinline__ void ffma2(unsigned long long& d, unsigned long long a, unsigned long long b) {
    asm("fma.rn.f32x2 %0, %1, %2, %0;" : "+l"(d) : "l"(a), "l"(b));
}
__device__ __forceinline__ unsigned long long bcast2(float w) {
    unsigned long long r;
    asm("mov.b64 %0, {%1, %1};" : "=l"(r) : "r"(__float_as_uint(w)));
    return r;
}
__device__ __forceinline__ float2 unpack2(unsigned long long p) {
    unsigned int lo, hi;
    asm("mov.b64 {%0, %1}, %2;" : "=r"(lo), "=r"(hi) : "l"(p));
    return make_float2(__uint_as_float(lo), __uint_as_float(hi));
}

// ---------------- kernel 1: v_shaped + weight transpose + zero joints ----------------
__global__ void k_prep(const float* __restrict__ vt, const float* __restrict__ sd,
                       const float* __restrict__ betas, const float* __restrict__ lbs) {
    if (blockIdx.x < 81) {
        if (blockIdx.x == 0 && threadIdx.x < NJ * 3) g_joints[threadIdx.x] = 0.f;
        int i = blockIdx.x * 256 + threadIdx.x;
        if (i >= NV * 3) return;
        float acc = vt[i];
        #pragma unroll
        for (int l = 0; l < NBD; l++) acc += betas[1 + l] * sd[i * NBD + l];
        g_vshaped[i] = acc * betas[0];
    } else {
        int v = (blockIdx.x - 81) * 256 + threadIdx.x;
        if (v >= NV) return;
        const float4* w4 = reinterpret_cast<const float4*>(lbs + (size_t)v * NJ);
        #pragma unroll
        for (int c = 0; c < 6; c++) {
            float4 q = w4[c];
            g_wT[(c*4+0) * NV + v] = q.x;
            g_wT[(c*4+1) * NV + v] = q.y;
            g_wT[(c*4+2) * NV + v] = q.z;
            g_wT[(c*4+3) * NV + v] = q.w;
        }
    }
}

// ---------------- kernel 2: joints = J_regressor @ v_shaped (split-V + atomics) ----------------
__global__ void __launch_bounds__(512) k_joints(const float* __restrict__ Jreg) {
    int j = blockIdx.x;          // 0..23
    int chunk = blockIdx.y;      // 0..3
    int tid = threadIdx.x;
    const int CH = (NV + 3) / 4; // 1723
    int v0 = chunk * CH;
    int v1 = min(v0 + CH, NV);
    float s0 = 0.f, s1 = 0.f, s2 = 0.f;
    for (int v = v0 + tid; v < v1; v += 512) {
        float w = __ldg(Jreg + j * NV + v);
        s0 += w * g_vshaped[v * 3 + 0];
        s1 += w * g_vshaped[v * 3 + 1];
        s2 += w * g_vshaped[v * 3 + 2];
    }
    #pragma unroll
    for (int off = 16; off > 0; off >>= 1) {
        s0 += __shfl_xor_sync(0xffffffff, s0, off);
        s1 += __shfl_xor_sync(0xffffffff, s1, off);
        s2 += __shfl_xor_sync(0xffffffff, s2, off);
    }
    __shared__ float red[16][3];
    int wid = tid >> 5, lane = tid & 31;
    if (lane == 0) { red[wid][0] = s0; red[wid][1] = s1; red[wid][2] = s2; }
    __syncthreads();
    if (wid == 0 && lane < 16) {
        float r0 = red[lane][0], r1 = red[lane][1], r2 = red[lane][2];
        #pragma unroll
        for (int off = 8; off > 0; off >>= 1) {
            r0 += __shfl_xor_sync(0xffff, r0, off);
            r1 += __shfl_xor_sync(0xffff, r1, off);
            r2 += __shfl_xor_sync(0xffff, r2, off);
        }
        if (lane == 0) {
            atomicAdd(&g_joints[j * 3 + 0], r0);
            atomicAdd(&g_joints[j * 3 + 1], r1);
            atomicAdd(&g_joints[j * 3 + 2], r2);
        }
    }
}

// ---------------- kernel 3: kinematic chain, one block per batch ----------------
__global__ void k_chain(const float* __restrict__ pose_wo,
                        const float* __restrict__ rbk, const float* __restrict__ rfr,
                        const float* __restrict__ lbk, const float* __restrict__ lfr,
                        const float* __restrict__ go,
                        float* __restrict__ out_J) {
    int b = blockIdx.x;
    int j = threadIdx.x;   // blockDim = 32, joints use 0..23
    __shared__ float sT[NJ][12];
    __shared__ float sM[NJ][12];

    if (j < NJ) {
        float p0, p1, p2;
        if (j == 0)      { p0 = go[b*3]; p1 = go[b*3+1]; p2 = go[b*3+2]; }
        else if (j <= 6) { int o = b*57 + (j-1)*3; p0 = pose_wo[o]; p1 = pose_wo[o+1]; p2 = pose_wo[o+2]; }
        else if (j == 7) { p0 = lbk[b*3]; p1 = lbk[b*3+1]; p2 = lbk[b*3+2]; }
        else if (j == 8) { p0 = rbk[b*3]; p1 = rbk[b*3+1]; p2 = rbk[b*3+2]; }
        else if (j == 9) { int o = b*57 + 18; p0 = pose_wo[o]; p1 = pose_wo[o+1]; p2 = pose_wo[o+2]; }
        else if (j == 10){ p0 = lfr[b]; p1 = 0.f; p2 = 0.f; }
        else if (j == 11){ p0 = rfr[b]; p1 = 0.f; p2 = 0.f; }
        else             { int o = b*57 + 21 + (j-12)*3; p0 = pose_wo[o]; p1 = pose_wo[o+1]; p2 = pose_wo[o+2]; }

        float a0 = p0 + 1e-8f, a1 = p1 + 1e-8f, a2 = p2 + 1e-8f;
        float ang = sqrtf(a0*a0 + a1*a1 + a2*a2);
        float inv = 1.f / ang;
        float rx = p0 * inv, ry = p1 * inv, rz = p2 * inv;
        float sn, cs;
        __sincosf(ang, &sn, &cs);
        float omc = 1.f - cs;
        sT[j][0] = 1.f - omc * (ry*ry + rz*rz);
        sT[j][1] = -sn*rz + omc*rx*ry;
        sT[j][2] =  sn*ry + omc*rx*rz;
        sT[j][3] =  sn*rz + omc*rx*ry;
        sT[j][4] = 1.f - omc * (rx*rx + rz*rz);
        sT[j][5] = -sn*rx + omc*ry*rz;
        sT[j][6] = -sn*ry + omc*rx*rz;
        sT[j][7] =  sn*rx + omc*ry*rz;
        sT[j][8] = 1.f - omc * (rx*rx + ry*ry);

        int par = c_parents[j];
        float jx = g_joints[j*3], jy = g_joints[j*3+1], jz = g_joints[j*3+2];
        if (par < 0) { sT[j][9] = jx; sT[j][10] = jy; sT[j][11] = jz; }
        else {
            sT[j][9]  = jx - g_joints[par*3];
            sT[j][10] = jy - g_joints[par*3+1];
            sT[j][11] = jz - g_joints[par*3+2];
        }
    }
    __syncwarp();

    if (j == 0) {
        #pragma unroll
        for (int m = 0; m < 12; m++) sM[0][m] = sT[0][m];
    }
    __syncwarp();

    #pragma unroll
    for (int lvl = 1; lvl <= 10; lvl++) {
        if (j < NJ && c_level[j] == lvl) {
            int par = c_parents[j];
            const float* P = sM[par];
            const float* L = sT[j];
            float* M = sM[j];
            M[0] = P[0]*L[0] + P[1]*L[3] + P[2]*L[6];
            M[1] = P[0]*L[1] + P[1]*L[4] + P[2]*L[7];
            M[2] = P[0]*L[2] + P[1]*L[5] + P[2]*L[8];
            M[3] = P[3]*L[0] + P[4]*L[3] + P[5]*L[6];
            M[4] = P[3]*L[1] + P[4]*L[4] + P[5]*L[7];
            M[5] = P[3]*L[2] + P[4]*L[5] + P[5]*L[8];
            M[6] = P[6]*L[0] + P[7]*L[3] + P[8]*L[6];
            M[7] = P[6]*L[1] + P[7]*L[4] + P[8]*L[7];
            M[8] = P[6]*L[2] + P[7]*L[5] + P[8]*L[8];
            M[9]  = P[0]*L[9] + P[1]*L[10] + P[2]*L[11] + P[9];
            M[10] = P[3]*L[9] + P[4]*L[10] + P[5]*L[11] + P[10];
            M[11] = P[6]*L[9] + P[7]*L[10] + P[8]*L[11] + P[11];
        }
        __syncwarp();
    }

    if (j < NJ) {
        const float* M = sM[j];
        out_J[(b*NJ + j)*3 + 0] = M[9];
        out_J[(b*NJ + j)*3 + 1] = M[10];
        out_J[(b*NJ + j)*3 + 2] = M[11];

        float jx = g_joints[j*3], jy = g_joints[j*3+1], jz = g_joints[j*3+2];
        float ibx = M[0]*jx + M[1]*jy + M[2]*jz;
        float iby = M[3]*jx + M[4]*jy + M[5]*jz;
        float ibz = M[6]*jx + M[7]*jy + M[8]*jz;
        float* Ao = g_A + (b*NJ + j) * 12;
        Ao[0]=M[0]; Ao[1]=M[1]; Ao[2]=M[2];
        Ao[3]=M[3]; Ao[4]=M[4]; Ao[5]=M[5];
        Ao[6]=M[6]; Ao[7]=M[7]; Ao[8]=M[8];
        Ao[9]  = M[9]  - ibx;
        Ao[10] = M[10] - iby;
        Ao[11] = M[11] - ibz;
    }
}

// ---------------- kernel 4: LBS verts (2/thread, double-buffered A) + plane blocks ----------------
__global__ void __launch_bounds__(128, 5) k_verts(const float* __restrict__ lbs,
                                                  const float* __restrict__ transl,
                                                  const int* __restrict__ bl, const int* __restrict__ fl,
                                                  const int* __restrict__ br, const int* __restrict__ fr,
                                                  const float* __restrict__ ipbl, const float* __restrict__ ipfl,
                                                  const float* __restrict__ ipbr, const float* __restrict__ ipfr,
                                                  float* __restrict__ out_verts,
                                                  float* __restrict__ out_plane) {
    __shared__ float sA[2][NJ * 12];
    int tid = threadIdx.x;
    const float4* gA4 = reinterpret_cast<const float4*>(g_A);

    if (blockIdx.y >= VB_Y) {
        // ======== plane block: one batch per block ========
        int b = (blockIdx.y - VB_Y) * VB_X + blockIdx.x;
        if (b >= NBATCH) return;
        if (tid < 72) reinterpret_cast<float4*>(sA[0])[tid] = gA4[b * 72 + tid];
        __syncthreads();
        const ulonglong2* sA2 = reinterpret_cast<const ulonglong2*>(sA[0]);
        float t0 = __ldg(transl + b*3), t1 = __ldg(transl + b*3+1), t2 = __ldg(transl + b*3+2);
        for (int p = tid; p < 4 * NP; p += 128) {
            int s = p / NP, l = p % NP;
            const int* ids = (s == 0) ? bl : (s == 1) ? fl : (s == 2) ? br : fr;
            const float* ip = (s == 0) ? ipbl : (s == 1) ? ipfl : (s == 2) ? ipbr : ipfr;
            int v = ids[l];
            unsigned long long A0[6];
            #pragma unroll
            for (int m = 0; m < 6; m++) A0[m] = 0ull;
            const float4* w4 = reinterpret_cast<const float4*>(lbs + (size_t)v * NJ);
            #pragma unroll
            for (int c = 0; c < 6; c++) {
                float4 wq = w4[c];
                float ws[4] = {wq.x, wq.y, wq.z, wq.w};
                #pragma unroll
                for (int q = 0; q < 4; q++) {
                    int j = c * 4 + q;
                    ulonglong2 p0 = sA2[j*3+0], p1 = sA2[j*3+1], p2 = sA2[j*3+2];
                    unsigned long long wp = bcast2(ws[q]);
                    ffma2(A0[0], wp, p0.x); ffma2(A0[1], wp, p0.y);
                    ffma2(A0[2], wp, p1.x); ffma2(A0[3], wp, p1.y);
                    ffma2(A0[4], wp, p2.x); ffma2(A0[5], wp, p2.y);
                }
            }
            float2 T01 = unpack2(A0[0]), T23 = unpack2(A0[1]), T45 = unpack2(A0[2]);
            float2 T67 = unpack2(A0[3]), T89 = unpack2(A0[4]), Tab = unpack2(A0[5]);
            const float* pt = ip + ((size_t)b * NP + l) * 3;
            float x = pt[0], y = pt[1], z = pt[2];
            float* o = out_plane + ((size_t)b * 4 * NP + p) * 3;
            o[0] = T01.x*x + T01.y*y + T23.x*z + T89.y + t0;
            o[1] = T23.y*x + T45.x*y + T45.y*z + Tab.x + t1;
            o[2] = T67.x*x + T67.y*y + T89.x*z + Tab.y + t2;
        }
        return;
    }

    // ======== verts block: 2 vertices/thread, BT batches, double-buffered A ========
    int v0 = blockIdx.x * 128 + tid;          // 0..3455 (< NV always)
    int v1 = v0 + 3456;
    bool has1 = v1 < NV;
    int vc1 = has1 ? v1 : 0;

    float w0[NJ], w1[NJ];
    #pragma unroll
    for (int j = 0; j < NJ; j++) {
        w0[j] = g_wT[j * NV + v0];
        w1[j] = g_wT[j * NV + vc1];
    }
    float x0 = g_vshaped[v0*3], y0 = g_vshaped[v0*3+1], z0 = g_vshaped[v0*3+2];
    float x1 = g_vshaped[vc1*3], y1 = g_vshaped[vc1*3+1], z1 = g_vshaped[vc1*3+2];

    int b0 = blockIdx.y * BT;
    if (tid < 72) reinterpret_cast<float4*>(sA[0])[tid] = gA4[(size_t)b0 * 72 + tid];
    __syncthreads();

    #pragma unroll 1
    for (int bb = 0; bb < BT; bb++) {
        int b = b0 + bb;
        int p = bb & 1;
        bool pre = (bb + 1 < BT) && (tid < 72);
        float4 nxt;
        if (pre) nxt = gA4[(size_t)(b + 1) * 72 + tid];

        const ulonglong2* sA2 = reinterpret_cast<const ulonglong2*>(sA[p]);
        unsigned long long A0[6], A1[6];
        #pragma unroll
        for (int m = 0; m < 6; m++) { A0[m] = 0ull; A1[m] = 0ull; }

        #pragma unroll
        for (int j = 0; j < NJ; j++) {
            ulonglong2 q0 = sA2[j*3+0], q1 = sA2[j*3+1], q2 = sA2[j*3+2];
            unsigned long long wp0 = bcast2(w0[j]);
            unsigned long long wp1 = bcast2(w1[j]);
            ffma2(A0[0], wp0, q0.x); ffma2(A0[1], wp0, q0.y);
            ffma2(A0[2], wp0, q1.x); ffma2(A0[3], wp0, q1.y);
            ffma2(A0[4], wp0, q2.x); ffma2(A0[5], wp0, q2.y);
            ffma2(A1[0], wp1, q0.x); ffma2(A1[1], wp1, q0.y);
            ffma2(A1[2], wp1, q1.x); ffma2(A1[3], wp1, q1.y);
            ffma2(A1[4], wp1, q2.x); ffma2(A1[5], wp1, q2.y);
        }

        float t0 = __ldg(transl + b*3), t1 = __ldg(transl + b*3+1), t2 = __ldg(transl + b*3+2);
        {
            float2 T01 = unpack2(A0[0]), T23 = unpack2(A0[1]), T45 = unpack2(A0[2]);
            float2 T67 = unpack2(A0[3]), T89 = unpack2(A0[4]), Tab = unpack2(A0[5]);
            float* o = out_verts + ((size_t)b * NV + v0) * 3;
            o[0] = T01.x*x0 + T01.y*y0 + T23.x*z0 + T89.y + t0;
            o[1] = T23.y*x0 + T45.x*y0 + T45.y*z0 + Tab.x + t1;
            o[2] = T67.x*x0 + T67.y*y0 + T89.x*z0 + Tab.y + t2;
        }
        if (has1) {
            float2 T01 = unpack2(A1[0]), T23 = unpack2(A1[1]), T45 = unpack2(A1[2]);
            float2 T67 = unpack2(A1[3]), T89 = unpack2(A1[4]), Tab = unpack2(A1[5]);
            float* o = out_verts + ((size_t)b * NV + v1) * 3;
            o[0] = T01.x*x1 + T01.y*y1 + T23.x*z1 + T89.y + t0;
            o[1] = T23.y*x1 + T45.x*y1 + T45.y*z1 + Tab.x + t1;
            o[2] = T67.x*x1 + T67.y*y1 + T89.x*z1 + Tab.y + t2;
        }

        if (pre) reinterpret_cast<float4*>(sA[1 - p])[tid] = nxt;
        __syncthreads();
    }
}

extern "C" void kernel_launch(void* const* d_in, const int* in_sizes, int n_in,
                              void* d_out, int out_size) {
    const float* v_template = (const float*)d_in[0];
    const float* shapedirs  = (const float*)d_in[1];
    const float* J_regressor= (const float*)d_in[2];
    const float* lbs        = (const float*)d_in[3];
    const float* betas      = (const float*)d_in[4];
    const float* pose_wo    = (const float*)d_in[5];
    const float* rbk        = (const float*)d_in[6];
    const float* rfr        = (const float*)d_in[7];
    const float* lbk        = (const float*)d_in[8];
    const float* lfr        = (const float*)d_in[9];
    const float* transl     = (const float*)d_in[10];
    const float* go         = (const float*)d_in[11];
    const float* ipbl       = (const float*)d_in[12];
    const float* ipfl       = (const float*)d_in[13];
    const float* ipbr       = (const float*)d_in[14];
    const float* ipfr       = (const float*)d_in[15];
    // d_in[16] = parents (int64) — hardcoded in c_parents
    const int* bl = (const int*)d_in[17];
    const int* br = (const int*)d_in[18];
    const int* fl = (const int*)d_in[19];
    const int* fr = (const int*)d_in[20];

    float* out = (float*)d_out;
    float* out_verts = out;                                   // B*NV*3
    float* out_J     = out + (size_t)NBATCH * NV * 3;         // B*NJ*3
    float* out_plane = out_J + (size_t)NBATCH * NJ * 3;       // B*4P*3

    k_prep<<<81 + 27, 256>>>(v_template, shapedirs, betas, lbs);
    dim3 gj(NJ, 4);
    k_joints<<<gj, 512>>>(J_regressor);
    k_chain<<<NBATCH, 32>>>(pose_wo, rbk, rfr, lbk, lfr, go, out_J);

    dim3 gv(VB_X, VB_Y + PL_Y);
    k_verts<<<gv, 128>>>(lbs, transl, bl, fl, br, fr, ipbl, ipfl, ipbr, ipfr,
                         out_verts, out_plane);
}

// round 7
// speedup vs baseline: 1.1735x; 1.1735x over previous
#include <cuda_runtime.h>

#define NV 6890
#define NJ 24
#define NBD 10
#define NBATCH 256
#define NP 100
#define BT 4            // batches per k_verts block
#define VB_Y 64         // NBATCH / BT
#define VB_X 18         // 18*128 = 2304 thread-columns, 3 verts/thread
#define VSTRIDE 2304
#define PL_Y 15         // 18*15 = 270 >= 256 plane blocks

// scratch (allocation-free rule: __device__ globals)
__device__ float g_vshaped[NV * 3];
__device__ float g_joints[NJ * 3];
__device__ float g_A[NBATCH * NJ * 12];   // per (b,j): R row-major [0..8], t [9..11]
__device__ float g_wT[NJ * NV];           // transposed lbs weights [j][v]

__constant__ int c_parents[NJ] = {-1,0,0,0,1,2,3,4,5,6,7,8,9,9,9,12,13,14,16,17,18,19,20,21};
__constant__ int c_level[NJ]   = { 0,1,1,1,2,2,2,3,3,3,4,4,4,4, 4, 5, 5, 5, 6, 6, 7, 8, 9,10};

// packed fp32x2 FMA: d = a*b + d  (FFMA2 — only reachable via PTX)
__device__ __forceinline__ void ffma2(unsigned long long& d, unsigned long long a, unsigned long long b) {
    asm("fma.rn.f32x2 %0, %1, %2, %0;" : "+l"(d) : "l"(a), "l"(b));
}
__device__ __forceinline__ unsigned long long bcast2(float w) {
    unsigned long long r;
    asm("mov.b64 %0, {%1, %1};" : "=l"(r) : "r"(__float_as_uint(w)));
    return r;
}
__device__ __forceinline__ float2 unpack2(unsigned long long p) {
    unsigned int lo, hi;
    asm("mov.b64 {%0, %1}, %2;" : "=r"(lo), "=r"(hi) : "l"(p));
    return make_float2(__uint_as_float(lo), __uint_as_float(hi));
}

// ---------------- kernel 1: v_shaped + weight transpose + zero joints ----------------
__global__ void k_prep(const float* __restrict__ vt, const float* __restrict__ sd,
                       const float* __restrict__ betas, const float* __restrict__ lbs) {
    if (blockIdx.x < 81) {
        if (blockIdx.x == 0 && threadIdx.x < NJ * 3) g_joints[threadIdx.x] = 0.f;
        int i = blockIdx.x * 256 + threadIdx.x;
        if (i >= NV * 3) return;
        float acc = vt[i];
        #pragma unroll
        for (int l = 0; l < NBD; l++) acc += betas[1 + l] * sd[i * NBD + l];
        g_vshaped[i] = acc * betas[0];
    } else {
        int v = (blockIdx.x - 81) * 256 + threadIdx.x;
        if (v >= NV) return;
        const float4* w4 = reinterpret_cast<const float4*>(lbs + (size_t)v * NJ);
        #pragma unroll
        for (int c = 0; c < 6; c++) {
            float4 q = w4[c];
            g_wT[(c*4+0) * NV + v] = q.x;
            g_wT[(c*4+1) * NV + v] = q.y;
            g_wT[(c*4+2) * NV + v] = q.z;
            g_wT[(c*4+3) * NV + v] = q.w;
        }
    }
}

// ---------------- kernel 2: joints = J_regressor @ v_shaped (split-V + atomics) ----------------
__global__ void __launch_bounds__(512) k_joints(const float* __restrict__ Jreg) {
    int j = blockIdx.x;          // 0..23
    int chunk = blockIdx.y;      // 0..3
    int tid = threadIdx.x;
    const int CH = (NV + 3) / 4; // 1723
    int v0 = chunk * CH;
    int v1 = min(v0 + CH, NV);
    float s0 = 0.f, s1 = 0.f, s2 = 0.f;
    for (int v = v0 + tid; v < v1; v += 512) {
        float w = __ldg(Jreg + j * NV + v);
        s0 += w * g_vshaped[v * 3 + 0];
        s1 += w * g_vshaped[v * 3 + 1];
        s2 += w * g_vshaped[v * 3 + 2];
    }
    #pragma unroll
    for (int off = 16; off > 0; off >>= 1) {
        s0 += __shfl_xor_sync(0xffffffff, s0, off);
        s1 += __shfl_xor_sync(0xffffffff, s1, off);
        s2 += __shfl_xor_sync(0xffffffff, s2, off);
    }
    __shared__ float red[16][3];
    int wid = tid >> 5, lane = tid & 31;
    if (lane == 0) { red[wid][0] = s0; red[wid][1] = s1; red[wid][2] = s2; }
    __syncthreads();
    if (wid == 0 && lane < 16) {
        float r0 = red[lane][0], r1 = red[lane][1], r2 = red[lane][2];
        #pragma unroll
        for (int off = 8; off > 0; off >>= 1) {
            r0 += __shfl_xor_sync(0xffff, r0, off);
            r1 += __shfl_xor_sync(0xffff, r1, off);
            r2 += __shfl_xor_sync(0xffff, r2, off);
        }
        if (lane == 0) {
            atomicAdd(&g_joints[j * 3 + 0], r0);
            atomicAdd(&g_joints[j * 3 + 1], r1);
            atomicAdd(&g_joints[j * 3 + 2], r2);
        }
    }
}

// ---------------- kernel 3: kinematic chain, one block per batch ----------------
__global__ void k_chain(const float* __restrict__ pose_wo,
                        const float* __restrict__ rbk, const float* __restrict__ rfr,
                        const float* __restrict__ lbk, const float* __restrict__ lfr,
                        const float* __restrict__ go,
                        float* __restrict__ out_J) {
    int b = blockIdx.x;
    int j = threadIdx.x;   // blockDim = 32, joints use 0..23
    __shared__ float sT[NJ][12];
    __shared__ float sM[NJ][12];

    if (j < NJ) {
        float p0, p1, p2;
        if (j == 0)      { p0 = go[b*3]; p1 = go[b*3+1]; p2 = go[b*3+2]; }
        else if (j <= 6) { int o = b*57 + (j-1)*3; p0 = pose_wo[o]; p1 = pose_wo[o+1]; p2 = pose_wo[o+2]; }
        else if (j == 7) { p0 = lbk[b*3]; p1 = lbk[b*3+1]; p2 = lbk[b*3+2]; }
        else if (j == 8) { p0 = rbk[b*3]; p1 = rbk[b*3+1]; p2 = rbk[b*3+2]; }
        else if (j == 9) { int o = b*57 + 18; p0 = pose_wo[o]; p1 = pose_wo[o+1]; p2 = pose_wo[o+2]; }
        else if (j == 10){ p0 = lfr[b]; p1 = 0.f; p2 = 0.f; }
        else if (j == 11){ p0 = rfr[b]; p1 = 0.f; p2 = 0.f; }
        else             { int o = b*57 + 21 + (j-12)*3; p0 = pose_wo[o]; p1 = pose_wo[o+1]; p2 = pose_wo[o+2]; }

        float a0 = p0 + 1e-8f, a1 = p1 + 1e-8f, a2 = p2 + 1e-8f;
        float ang = sqrtf(a0*a0 + a1*a1 + a2*a2);
        float inv = 1.f / ang;
        float rx = p0 * inv, ry = p1 * inv, rz = p2 * inv;
        float sn, cs;
        __sincosf(ang, &sn, &cs);
        float omc = 1.f - cs;
        sT[j][0] = 1.f - omc * (ry*ry + rz*rz);
        sT[j][1] = -sn*rz + omc*rx*ry;
        sT[j][2] =  sn*ry + omc*rx*rz;
        sT[j][3] =  sn*rz + omc*rx*ry;
        sT[j][4] = 1.f - omc * (rx*rx + rz*rz);
        sT[j][5] = -sn*rx + omc*ry*rz;
        sT[j][6] = -sn*ry + omc*rx*rz;
        sT[j][7] =  sn*rx + omc*ry*rz;
        sT[j][8] = 1.f - omc * (rx*rx + ry*ry);

        int par = c_parents[j];
        float jx = g_joints[j*3], jy = g_joints[j*3+1], jz = g_joints[j*3+2];
        if (par < 0) { sT[j][9] = jx; sT[j][10] = jy; sT[j][11] = jz; }
        else {
            sT[j][9]  = jx - g_joints[par*3];
            sT[j][10] = jy - g_joints[par*3+1];
            sT[j][11] = jz - g_joints[par*3+2];
        }
    }
    __syncwarp();

    if (j == 0) {
        #pragma unroll
        for (int m = 0; m < 12; m++) sM[0][m] = sT[0][m];
    }
    __syncwarp();

    #pragma unroll
    for (int lvl = 1; lvl <= 10; lvl++) {
        if (j < NJ && c_level[j] == lvl) {
            int par = c_parents[j];
            const float* P = sM[par];
            const float* L = sT[j];
            float* M = sM[j];
            M[0] = P[0]*L[0] + P[1]*L[3] + P[2]*L[6];
            M[1] = P[0]*L[1] + P[1]*L[4] + P[2]*L[7];
            M[2] = P[0]*L[2] + P[1]*L[5] + P[2]*L[8];
            M[3] = P[3]*L[0] + P[4]*L[3] + P[5]*L[6];
            M[4] = P[3]*L[1] + P[4]*L[4] + P[5]*L[7];
            M[5] = P[3]*L[2] + P[4]*L[5] + P[5]*L[8];
            M[6] = P[6]*L[0] + P[7]*L[3] + P[8]*L[6];
            M[7] = P[6]*L[1] + P[7]*L[4] + P[8]*L[7];
            M[8] = P[6]*L[2] + P[7]*L[5] + P[8]*L[8];
            M[9]  = P[0]*L[9] + P[1]*L[10] + P[2]*L[11] + P[9];
            M[10] = P[3]*L[9] + P[4]*L[10] + P[5]*L[11] + P[10];
            M[11] = P[6]*L[9] + P[7]*L[10] + P[8]*L[11] + P[11];
        }
        __syncwarp();
    }

    if (j < NJ) {
        const float* M = sM[j];
        out_J[(b*NJ + j)*3 + 0] = M[9];
        out_J[(b*NJ + j)*3 + 1] = M[10];
        out_J[(b*NJ + j)*3 + 2] = M[11];

        float jx = g_joints[j*3], jy = g_joints[j*3+1], jz = g_joints[j*3+2];
        float ibx = M[0]*jx + M[1]*jy + M[2]*jz;
        float iby = M[3]*jx + M[4]*jy + M[5]*jz;
        float ibz = M[6]*jx + M[7]*jy + M[8]*jz;
        float* Ao = g_A + (b*NJ + j) * 12;
        Ao[0]=M[0]; Ao[1]=M[1]; Ao[2]=M[2];
        Ao[3]=M[3]; Ao[4]=M[4]; Ao[5]=M[5];
        Ao[6]=M[6]; Ao[7]=M[7]; Ao[8]=M[8];
        Ao[9]  = M[9]  - ibx;
        Ao[10] = M[10] - iby;
        Ao[11] = M[11] - ibz;
    }
}

// ---------------- kernel 4: LBS verts (3/thread, double-buffered A) + plane blocks ----------------
__global__ void __launch_bounds__(128, 3) k_verts(const float* __restrict__ lbs,
                                                  const float* __restrict__ transl,
                                                  const int* __restrict__ bl, const int* __restrict__ fl,
                                                  const int* __restrict__ br, const int* __restrict__ fr,
                                                  const float* __restrict__ ipbl, const float* __restrict__ ipfl,
                                                  const float* __restrict__ ipbr, const float* __restrict__ ipfr,
                                                  float* __restrict__ out_verts,
                                                  float* __restrict__ out_plane) {
    __shared__ float sA[2][NJ * 12];
    int tid = threadIdx.x;
    const float4* gA4 = reinterpret_cast<const float4*>(g_A);

    if (blockIdx.y >= VB_Y) {
        // ======== plane block: one batch per block ========
        int b = (blockIdx.y - VB_Y) * VB_X + blockIdx.x;
        if (b >= NBATCH) return;
        if (tid < 72) reinterpret_cast<float4*>(sA[0])[tid] = gA4[b * 72 + tid];
        __syncthreads();
        const ulonglong2* sA2 = reinterpret_cast<const ulonglong2*>(sA[0]);
        float t0 = __ldg(transl + b*3), t1 = __ldg(transl + b*3+1), t2 = __ldg(transl + b*3+2);
        for (int p = tid; p < 4 * NP; p += 128) {
            int s = p / NP, l = p % NP;
            const int* ids = (s == 0) ? bl : (s == 1) ? fl : (s == 2) ? br : fr;
            const float* ip = (s == 0) ? ipbl : (s == 1) ? ipfl : (s == 2) ? ipbr : ipfr;
            int v = ids[l];
            unsigned long long A0[6];
            #pragma unroll
            for (int m = 0; m < 6; m++) A0[m] = 0ull;
            const float4* w4 = reinterpret_cast<const float4*>(lbs + (size_t)v * NJ);
            #pragma unroll
            for (int c = 0; c < 6; c++) {
                float4 wq = w4[c];
                float ws[4] = {wq.x, wq.y, wq.z, wq.w};
                #pragma unroll
                for (int q = 0; q < 4; q++) {
                    int j = c * 4 + q;
                    ulonglong2 p0 = sA2[j*3+0], p1 = sA2[j*3+1], p2 = sA2[j*3+2];
                    unsigned long long wp = bcast2(ws[q]);
                    ffma2(A0[0], wp, p0.x); ffma2(A0[1], wp, p0.y);
                    ffma2(A0[2], wp, p1.x); ffma2(A0[3], wp, p1.y);
                    ffma2(A0[4], wp, p2.x); ffma2(A0[5], wp, p2.y);
                }
            }
            float2 T01 = unpack2(A0[0]), T23 = unpack2(A0[1]), T45 = unpack2(A0[2]);
            float2 T67 = unpack2(A0[3]), T89 = unpack2(A0[4]), Tab = unpack2(A0[5]);
            const float* pt = ip + ((size_t)b * NP + l) * 3;
            float x = pt[0], y = pt[1], z = pt[2];
            float* o = out_plane + ((size_t)b * 4 * NP + p) * 3;
            o[0] = T01.x*x + T01.y*y + T23.x*z + T89.y + t0;
            o[1] = T23.y*x + T45.x*y + T45.y*z + Tab.x + t1;
            o[2] = T67.x*x + T67.y*y + T89.x*z + Tab.y + t2;
        }
        return;
    }

    // ======== verts block: 3 vertices/thread, BT batches, double-buffered A ========
    int v0 = blockIdx.x * 128 + tid;          // < 2304
    int v1 = v0 + VSTRIDE;                    // < 4608
    int v2 = v0 + 2 * VSTRIDE;                // may exceed NV
    bool has2 = v2 < NV;
    int vc2 = has2 ? v2 : 0;

    float w0[NJ], w1[NJ], w2[NJ];
    #pragma unroll
    for (int j = 0; j < NJ; j++) {
        w0[j] = g_wT[j * NV + v0];
        w1[j] = g_wT[j * NV + v1];
        w2[j] = g_wT[j * NV + vc2];
    }
    float x0 = g_vshaped[v0*3], y0 = g_vshaped[v0*3+1], z0 = g_vshaped[v0*3+2];
    float x1 = g_vshaped[v1*3], y1 = g_vshaped[v1*3+1], z1 = g_vshaped[v1*3+2];
    float x2 = g_vshaped[vc2*3], y2 = g_vshaped[vc2*3+1], z2 = g_vshaped[vc2*3+2];

    int b0 = blockIdx.y * BT;
    if (tid < 72) reinterpret_cast<float4*>(sA[0])[tid] = gA4[(size_t)b0 * 72 + tid];
    __syncthreads();

    #pragma unroll 1
    for (int bb = 0; bb < BT; bb++) {
        int b = b0 + bb;
        int p = bb & 1;
        bool pre = (bb + 1 < BT) && (tid < 72);
        float4 nxt;
        if (pre) nxt = gA4[(size_t)(b + 1) * 72 + tid];

        const ulonglong2* sA2 = reinterpret_cast<const ulonglong2*>(sA[p]);
        unsigned long long A0[6], A1[6], A2[6];
        #pragma unroll
        for (int m = 0; m < 6; m++) { A0[m] = 0ull; A1[m] = 0ull; A2[m] = 0ull; }

        #pragma unroll
        for (int j = 0; j < NJ; j++) {
            ulonglong2 q0 = sA2[j*3+0], q1 = sA2[j*3+1], q2 = sA2[j*3+2];
            unsigned long long wp0 = bcast2(w0[j]);
            unsigned long long wp1 = bcast2(w1[j]);
            unsigned long long wp2 = bcast2(w2[j]);
            ffma2(A0[0], wp0, q0.x); ffma2(A0[1], wp0, q0.y);
            ffma2(A0[2], wp0, q1.x); ffma2(A0[3], wp0, q1.y);
            ffma2(A0[4], wp0, q2.x); ffma2(A0[5], wp0, q2.y);
            ffma2(A1[0], wp1, q0.x); ffma2(A1[1], wp1, q0.y);
            ffma2(A1[2], wp1, q1.x); ffma2(A1[3], wp1, q1.y);
            ffma2(A1[4], wp1, q2.x); ffma2(A1[5], wp1, q2.y);
            ffma2(A2[0], wp2, q0.x); ffma2(A2[1], wp2, q0.y);
            ffma2(A2[2], wp2, q1.x); ffma2(A2[3], wp2, q1.y);
            ffma2(A2[4], wp2, q2.x); ffma2(A2[5], wp2, q2.y);
        }

        float t0 = __ldg(transl + b*3), t1 = __ldg(transl + b*3+1), t2 = __ldg(transl + b*3+2);
        {
            float2 T01 = unpack2(A0[0]), T23 = unpack2(A0[1]), T45 = unpack2(A0[2]);
            float2 T67 = unpack2(A0[3]), T89 = unpack2(A0[4]), Tab = unpack2(A0[5]);
            float* o = out_verts + ((size_t)b * NV + v0) * 3;
            o[0] = T01.x*x0 + T01.y*y0 + T23.x*z0 + T89.y + t0;
            o[1] = T23.y*x0 + T45.x*y0 + T45.y*z0 + Tab.x + t1;
            o[2] = T67.x*x0 + T67.y*y0 + T89.x*z0 + Tab.y + t2;
        }
        {
            float2 T01 = unpack2(A1[0]), T23 = unpack2(A1[1]), T45 = unpack2(A1[2]);
            float2 T67 = unpack2(A1[3]), T89 = unpack2(A1[4]), Tab = unpack2(A1[5]);
            float* o = out_verts + ((size_t)b * NV + v1) * 3;
            o[0] = T01.x*x1 + T01.y*y1 + T23.x*z1 + T89.y + t0;
            o[1] = T23.y*x1 + T45.x*y1 + T45.y*z1 + Tab.x + t1;
            o[2] = T67.x*x1 + T67.y*y1 + T89.x*z1 + Tab.y + t2;
        }
        if (has2) {
            float2 T01 = unpack2(A2[0]), T23 = unpack2(A2[1]), T45 = unpack2(A2[2]);
            float2 T67 = unpack2(A2[3]), T89 = unpack2(A2[4]), Tab = unpack2(A2[5]);
            float* o = out_verts + ((size_t)b * NV + v2) * 3;
            o[0] = T01.x*x2 + T01.y*y2 + T23.x*z2 + T89.y + t0;
            o[1] = T23.y*x2 + T45.x*y2 + T45.y*z2 + Tab.x + t1;
            o[2] = T67.x*x2 + T67.y*y2 + T89.x*z2 + Tab.y + t2;
        }

        if (pre) reinterpret_cast<float4*>(sA[1 - p])[tid] = nxt;
        __syncthreads();
    }
}

extern "C" void kernel_launch(void* const* d_in, const int* in_sizes, int n_in,
                              void* d_out, int out_size) {
    const float* v_template = (const float*)d_in[0];
    const float* shapedirs  = (const float*)d_in[1];
    const float* J_regressor= (const float*)d_in[2];
    const float* lbs        = (const float*)d_in[3];
    const float* betas      = (const float*)d_in[4];
    const float* pose_wo    = (const float*)d_in[5];
    const float* rbk        = (const float*)d_in[6];
    const float* rfr        = (const float*)d_in[7];
    const float* lbk        = (const float*)d_in[8];
    const float* lfr        = (const float*)d_in[9];
    const float* transl     = (const float*)d_in[10];
    const float* go         = (const float*)d_in[11];
    const float* ipbl       = (const float*)d_in[12];
    const float* ipfl       = (const float*)d_in[13];
    const float* ipbr       = (const float*)d_in[14];
    const float* ipfr       = (const float*)d_in[15];
    // d_in[16] = parents (int64) — hardcoded in c_parents
    const int* bl = (const int*)d_in[17];
    const int* br = (const int*)d_in[18];
    const int* fl = (const int*)d_in[19];
    const int* fr = (const int*)d_in[20];

    float* out = (float*)d_out;
    float* out_verts = out;                                   // B*NV*3
    float* out_J     = out + (size_t)NBATCH * NV * 3;         // B*NJ*3
    float* out_plane = out_J + (size_t)NBATCH * NJ * 3;       // B*4P*3

    k_prep<<<81 + 27, 256>>>(v_template, shapedirs, betas, lbs);
    dim3 gj(NJ, 4);
    k_joints<<<gj, 512>>>(J_regressor);
    k_chain<<<NBATCH, 32>>>(pose_wo, rbk, rfr, lbk, lfr, go, out_J);

    dim3 gv(VB_X, VB_Y + PL_Y);
    k_verts<<<gv, 128>>>(lbs, transl, bl, fl, br, fr, ipbl, ipfl, ipbr, ipfr,
                         out_verts, out_plane);
}